// round 4
// baseline (speedup 1.0000x reference)
#include <cuda_runtime.h>

// Bilinear 2x upsample, NHWC f32. Row-looped: each thread walks J row-groups,
// carrying the bottom input row (and its horizontal lerps) into the next
// iteration's top row, and prefetching the next row before storing.
// in : (8, 256, 256, 64), out: (8, 512, 512, 64)

static constexpr int IN_H  = 256;
static constexpr int IN_W  = 256;
static constexpr int OUT_H = 512;
static constexpr int OUT_W = 512;
static constexpr int CV    = 16;   // float4 vectors per pixel (C=64)
static constexpr int J     = 8;    // row-groups per block

__device__ __forceinline__ float4 lerp4(float4 a, float4 b, float wb) {
    float wa = 1.0f - wb;
    float4 r;
    r.x = a.x * wa + b.x * wb;
    r.y = a.y * wa + b.y * wb;
    r.z = a.z * wa + b.z * wb;
    r.w = a.w * wa + b.w * wb;
    return r;
}

__global__ __launch_bounds__(256)
void bilerp2x_loop_kernel(const float4* __restrict__ in, float4* __restrict__ out) {
    int cvec  = threadIdx.x;                    // 0..15
    int i     = blockIdx.x * 16 + threadIdx.y;  // column group 0..255
    int jbase = blockIdx.y * J;                 // row group base
    int b     = blockIdx.z;

    int ii   = i - 1;
    long off_lo = (long)max(ii, 0) * CV;
    long off_hi = (long)(ii + 1) * CV;          // i=0 -> 0 (== lo), i=255 -> 255
    bool wxa = (i > 0);
    bool ex  = (i == 255);

    const float4* inb = in + (long)b * IN_H * IN_W * CV + cvec;

    // top row = max(jbase-1,0), bottom row = jbase
    const float4* rt = inb + (long)max(jbase - 1, 0) * (IN_W * CV);
    float4 t0 = __ldg(rt + off_lo);
    float4 t1 = __ldg(rt + off_hi);
    const float4* rb = inb + (long)jbase * (IN_W * CV);
    float4 b0 = __ldg(rb + off_lo);
    float4 b1 = __ldg(rb + off_hi);

    float4 ta = lerp4(t0, t1, 0.25f);
    float4 tb = lerp4(t0, t1, 0.75f);

    float4* outb = out + (long)b * OUT_H * OUT_W * CV + cvec;
    long oxa   = (long)(2 * i - 1) * CV;
    long oxb   = (long)(2 * i) * CV;
    long ox511 = (long)511 * CV;

    #pragma unroll
    for (int s = 0; s < J; ++s) {
        int j = jbase + s;

        // prefetch next bottom row (clamped; last block's last iter re-reads row 255 from L1)
        int y_next = min(j + 1, IN_H - 1);
        const float4* rn = inb + (long)y_next * (IN_W * CV);
        float4 n0 = __ldg(rn + off_lo);
        float4 n1 = __ldg(rn + off_hi);

        float4 ba = lerp4(b0, b1, 0.25f);
        float4 bb = lerp4(b0, b1, 0.75f);

        if (j > 0) {   // output row 2j-1, dy = 0.25
            float4* row = outb + (long)(2 * j - 1) * (OUT_W * CV);
            if (wxa) __stcs(row + oxa, lerp4(ta, ba, 0.25f));
            __stcs(row + oxb, lerp4(tb, bb, 0.25f));
            if (ex)  __stcs(row + ox511, lerp4(t1, b1, 0.25f));
        }
        {              // output row 2j, dy = 0.75
            float4* row = outb + (long)(2 * j) * (OUT_W * CV);
            if (wxa) __stcs(row + oxa, lerp4(ta, ba, 0.75f));
            __stcs(row + oxb, lerp4(tb, bb, 0.75f));
            if (ex)  __stcs(row + ox511, lerp4(t1, b1, 0.75f));
        }
        if (j == IN_H - 1) {  // output row 511: pure row-255 horizontal lerps
            float4* row = outb + (long)511 * (OUT_W * CV);
            if (wxa) __stcs(row + oxa, ba);
            __stcs(row + oxb, bb);
            if (ex)  __stcs(row + ox511, b1);
        }

        // rotate: bottom becomes top
        ta = ba; tb = bb; t1 = b1;
        b0 = n0; b1 = n1;
    }
}

extern "C" void kernel_launch(void* const* d_in, const int* in_sizes, int n_in,
                              void* d_out, int out_size) {
    const float4* in  = (const float4*)d_in[0];
    float4*       out = (float4*)d_out;

    dim3 block(16, 16);                 // tx = cvec, ty = column group
    dim3 grid(16, IN_H / J, 8);         // 16 x 32 x 8 = 4096 blocks
    bilerp2x_loop_kernel<<<grid, block>>>(in, out);
}

// round 5
// speedup vs baseline: 1.0408x; 1.0408x over previous
#include <cuda_runtime.h>

// Bilinear 2x upsample, NHWC f32. Each thread handles TWO adjacent column
// groups (i0=2p, i1=2p+1) of one row group: the shared middle input column is
// loaded once (6 loads, 8 stores per thread). Edge columns/rows folded in.
// in : (8, 256, 256, 64), out: (8, 512, 512, 64)

static constexpr int IN_H  = 256;
static constexpr int IN_W  = 256;
static constexpr int OUT_H = 512;
static constexpr int OUT_W = 512;
static constexpr int CV    = 16;   // float4 vectors per pixel (C=64)

__device__ __forceinline__ float4 lerp4(float4 a, float4 b, float wb) {
    float wa = 1.0f - wb;
    float4 r;
    r.x = a.x * wa + b.x * wb;
    r.y = a.y * wa + b.y * wb;
    r.z = a.z * wa + b.z * wb;
    r.w = a.w * wa + b.w * wb;
    return r;
}

__global__ __launch_bounds__(256)
void bilerp2x_x2_kernel(const float4* __restrict__ in, float4* __restrict__ out) {
    int cvec = threadIdx.x;                       // 0..15
    int p    = blockIdx.x * 16 + threadIdx.y;     // column pair group, 0..127
    int j    = blockIdx.y;                        // row group, 0..255
    int b    = blockIdx.z;

    int i0 = 2 * p;                               // 0..254
    // columns needed: cl = max(i0-1,0), cm = i0, ch = i0+1 (<=255)
    long off_l = (long)max(i0 - 1, 0) * CV;
    long off_m = (long)i0 * CV;
    long off_h = (long)(i0 + 1) * CV;

    int jj   = j - 1;
    int y_lo = max(jj, 0);
    int y_hi = jj + 1;                            // j<=255 -> <=255

    const float4* inb = in + (long)b * IN_H * IN_W * CV + cvec;
    const float4* rt  = inb + (long)y_lo * (IN_W * CV);
    const float4* rb  = inb + (long)y_hi * (IN_W * CV);

    // 6 independent loads, front-batched
    float4 tl = __ldg(rt + off_l);
    float4 tm = __ldg(rt + off_m);
    float4 th = __ldg(rt + off_h);
    float4 bl = __ldg(rb + off_l);
    float4 bm = __ldg(rb + off_m);
    float4 bh = __ldg(rb + off_h);

    // horizontal lerps
    float4 ta0 = lerp4(tl, tm, 0.25f);   // ox = 2*i0-1
    float4 tb0 = lerp4(tl, tm, 0.75f);   // ox = 2*i0
    float4 ta1 = lerp4(tm, th, 0.25f);   // ox = 2*i0+1
    float4 tb1 = lerp4(tm, th, 0.75f);   // ox = 2*i0+2
    float4 ba0 = lerp4(bl, bm, 0.25f);
    float4 bb0 = lerp4(bl, bm, 0.75f);
    float4 ba1 = lerp4(bm, bh, 0.25f);
    float4 bb1 = lerp4(bm, bh, 0.75f);

    bool wx0 = (p > 0);          // ox = 2*i0-1 valid unless i0 == 0
    bool wy0 = (j > 0);
    bool ex  = (p == 127);       // also emit ox=511 (col-255 vertical lerp)
    bool ey  = (j == 255);       // also emit oy=511 (row-255 horizontal lerp)

    long oxm1  = (long)(2 * i0 - 1) * CV;
    long ox0   = (long)(2 * i0)     * CV;
    long ox1   = (long)(2 * i0 + 1) * CV;
    long ox2   = (long)(2 * i0 + 2) * CV;
    long ox511 = (long)511 * CV;

    float4* outb = out + (long)b * OUT_H * OUT_W * CV + cvec;

    if (wy0) {  // output row 2j-1, dy = 0.25
        float4* row = outb + (long)(2 * j - 1) * (OUT_W * CV);
        if (wx0) __stcs(row + oxm1, lerp4(ta0, ba0, 0.25f));
        __stcs(row + ox0, lerp4(tb0, bb0, 0.25f));
        __stcs(row + ox1, lerp4(ta1, ba1, 0.25f));
        __stcs(row + ox2, lerp4(tb1, bb1, 0.25f));
        if (ex)  __stcs(row + ox511, lerp4(th, bh, 0.25f));
    }
    {           // output row 2j, dy = 0.75
        float4* row = outb + (long)(2 * j) * (OUT_W * CV);
        if (wx0) __stcs(row + oxm1, lerp4(ta0, ba0, 0.75f));
        __stcs(row + ox0, lerp4(tb0, bb0, 0.75f));
        __stcs(row + ox1, lerp4(ta1, ba1, 0.75f));
        __stcs(row + ox2, lerp4(tb1, bb1, 0.75f));
        if (ex)  __stcs(row + ox511, lerp4(th, bh, 0.75f));
    }
    if (ey) {   // output row 511: pure row-255 horizontal lerps
        float4* row = outb + (long)511 * (OUT_W * CV);
        if (wx0) __stcs(row + oxm1, ba0);
        __stcs(row + ox0, bb0);
        __stcs(row + ox1, ba1);
        __stcs(row + ox2, bb1);
        if (ex)  __stcs(row + ox511, bh);
    }
}

extern "C" void kernel_launch(void* const* d_in, const int* in_sizes, int n_in,
                              void* d_out, int out_size) {
    const float4* in  = (const float4*)d_in[0];
    float4*       out = (float4*)d_out;

    dim3 block(16, 16);          // tx = cvec, ty = column pair group
    dim3 grid(8, 256, 8);        // 128 column-pair groups, 256 row groups, 8 batches
    bilerp2x_x2_kernel<<<grid, block>>>(in, out);
}